// round 11
// baseline (speedup 1.0000x reference)
#include <cuda_runtime.h>
#include <cuda_bf16.h>
#include <cstdint>

// GaussianKernel: N=32, R=128, F=128
// Gram form: D[i,j] = ||u_i||^2 - 2 u_i.v_j + ||v_j||^2,  u = x1 - mean, v = x2
// out = softmax_j( exp( exp(-D/(2 sigma^2)) ) )
//
// 128 blocks (1/SM), 256 threads = 8 warps.
// 2-D warp partition: warp w owns 32i x 16j (j in [16w,16w+16)).
// lane = i8*4 + j4; thread tile 4i x 4j: i = i8+8r, j = 16w+j4+4q.
// b-loads: 8-way broadcast, 1 wavefront. a-loads: 8 rows, padded -> 1 wavefront.
// Norms fused into fills (shfl trees). Softmax via quad-shfl + pd[32][8].

#define N_B 32
#define R_DIM 128
#define F_DIM 128
#define TIB 32
#define SSTR 132        // padded row stride (floats)

__device__ __forceinline__ unsigned long long f32x2_fma(unsigned long long a, unsigned long long b, unsigned long long c) {
    unsigned long long r;
    asm("fma.rn.f32x2 %0, %1, %2, %3;" : "=l"(r) : "l"(a), "l"(b), "l"(c));
    return r;
}
__device__ __forceinline__ void f32x2_unpack(unsigned long long u, float& lo, float& hi) {
    asm("mov.b64 {%0, %1}, %2;" : "=f"(lo), "=f"(hi) : "l"(u));
}

// exp(x) for x in [0,1]: Taylor degree 10 (Horner). |err| <= 2.8e-8 abs.
__device__ __forceinline__ float exp01(float x) {
    float r = fmaf(2.75573192e-7f, x, 2.75573192e-6f);
    r = fmaf(r, x, 2.48015873e-5f);
    r = fmaf(r, x, 1.98412698e-4f);
    r = fmaf(r, x, 1.38888889e-3f);
    r = fmaf(r, x, 8.33333333e-3f);
    r = fmaf(r, x, 4.16666667e-2f);
    r = fmaf(r, x, 1.66666667e-1f);
    r = fmaf(r, x, 0.5f);
    r = fmaf(r, x, 1.0f);
    r = fmaf(r, x, 1.0f);
    return r;
}

__device__ __forceinline__ float warp_tree_sum(float s) {
    #pragma unroll
    for (int o = 16; o > 0; o >>= 1)
        s += __shfl_xor_sync(0xffffffffu, s, o);
    return s;
}

__global__ void __launch_bounds__(256)
gaussian_gram_v11(const float4* __restrict__ x1,
                  const float4* __restrict__ x2,
                  const float* __restrict__ sigma,
                  const float* __restrict__ mean,
                  float* __restrict__ out) {
    extern __shared__ float smem[];
    float* x2s   = smem;                          // [128][132]  v
    float* x1s   = x2s + R_DIM * SSTR;            // [32][132]   u = x1 - mean
    float* normu = x1s + TIB * SSTR;              // [32]
    float* normv = normu + TIB;                   // [128]
    float* pd    = normv + R_DIM;                 // [32][8] per-warp row partials

    const int n    = blockIdx.y;
    const int i0   = blockIdx.x * TIB;
    const int t    = threadIdx.x;
    const int lane = t & 31;
    const int w    = t >> 5;                      // warp: j-range [16w, 16w+16)
    const int i8   = lane >> 2;                   // i = i8 + 8r
    const int j4   = lane & 3;                    // j = 16w + j4 + 4q

    const float mn = mean[0];
    const float sg = sigma[0];
    const float inv2s2 = 1.0f / (2.0f * sg * sg);

    // ---- batched fill: ALL LDGs first (MLP=20), then STS + fused norms ----
    {
        const float4* x2g = x2 + (size_t)n * (R_DIM * F_DIM / 4);
        const float4* x1g = x1 + ((size_t)n * R_DIM + i0) * (F_DIM / 4);
        float4 vb[16], ub[4];
        #pragma unroll
        for (int it = 0; it < 16; ++it) vb[it] = x2g[t + 256 * it];
        #pragma unroll
        for (int it = 0; it < 4; ++it)  ub[it] = x1g[t + 256 * it];

        #pragma unroll
        for (int it = 0; it < 16; ++it) {
            int idx4 = t + 256 * it;
            int row  = idx4 >> 5;                 // lane-invariant per warp
            int c4   = idx4 & 31;
            float4 v = vb[it];
            *(float4*)&x2s[row * SSTR + c4 * 4] = v;
            float sq = v.x * v.x;
            sq = fmaf(v.y, v.y, sq);
            sq = fmaf(v.z, v.z, sq);
            sq = fmaf(v.w, v.w, sq);
            sq = warp_tree_sum(sq);
            if (lane == 0) normv[row] = sq;
        }
        #pragma unroll
        for (int it = 0; it < 4; ++it) {
            int idx4 = t + 256 * it;
            int row  = idx4 >> 5;
            int c4   = idx4 & 31;
            float4 v = ub[it];
            float4 u = make_float4(v.x - mn, v.y - mn, v.z - mn, v.w - mn);
            *(float4*)&x1s[row * SSTR + c4 * 4] = u;
            float sq = u.x * u.x;
            sq = fmaf(u.y, u.y, sq);
            sq = fmaf(u.z, u.z, sq);
            sq = fmaf(u.w, u.w, sq);
            sq = warp_tree_sum(sq);
            if (lane == 0) normu[row] = sq;
        }
    }
    __syncthreads();

    // ---- main loop: 4i x 4j tile, software-pipelined ----
    unsigned long long acc[4][4];                 // [r][q]
    #pragma unroll
    for (int r = 0; r < 4; ++r)
        #pragma unroll
        for (int q = 0; q < 4; ++q) acc[r][q] = 0ull;

    // b rows: 16w + j4 + 4q ; a rows: i8 + 8r
    const ulonglong2* brow = (const ulonglong2*)&x2s[(16 * w + j4) * SSTR];
    const ulonglong2* arow = (const ulonglong2*)&x1s[i8 * SSTR];
    const int bq = 4 * SSTR / 4;                  // ull2 units per 4 rows
    const int ar = 8 * SSTR / 4;                  // ull2 units per 8 rows

    ulonglong2 bc[4], ac[4], bn[4], an[4];
    #pragma unroll
    for (int q = 0; q < 4; ++q) bc[q] = brow[q * bq];
    #pragma unroll
    for (int r = 0; r < 4; ++r) ac[r] = arow[r * ar];

    #pragma unroll 8
    for (int f4 = 0; f4 < F_DIM / 4; ++f4) {
        if (f4 + 1 < F_DIM / 4) {
            #pragma unroll
            for (int q = 0; q < 4; ++q) bn[q] = brow[q * bq + f4 + 1];
            #pragma unroll
            for (int r = 0; r < 4; ++r) an[r] = arow[r * ar + f4 + 1];
        }
        #pragma unroll
        for (int r = 0; r < 4; ++r)
            #pragma unroll
            for (int q = 0; q < 4; ++q) {
                acc[r][q] = f32x2_fma(ac[r].x, bc[q].x, acc[r][q]);
                acc[r][q] = f32x2_fma(ac[r].y, bc[q].y, acc[r][q]);
            }
        #pragma unroll
        for (int q = 0; q < 4; ++q) bc[q] = bn[q];
        #pragma unroll
        for (int r = 0; r < 4; ++r) ac[r] = an[r];
    }

    // ---- kernel value + partial row sums ----
    float nv[4];
    #pragma unroll
    for (int q = 0; q < 4; ++q) nv[q] = normv[16 * w + j4 + 4 * q];
    float nu[4];
    #pragma unroll
    for (int r = 0; r < 4; ++r) nu[r] = normu[i8 + 8 * r];

    float ex[4][4];
    #pragma unroll
    for (int r = 0; r < 4; ++r) {
        float s = 0.0f;
        #pragma unroll
        for (int q = 0; q < 4; ++q) {
            float lo, hi; f32x2_unpack(acc[r][q], lo, hi);
            float D = fmaf(-2.0f, lo + hi, nu[r] + nv[q]);
            D = fmaxf(D, 0.0f);
            float k = __expf(-D * inv2s2);        // in (0,1]
            ex[r][q] = exp01(k);                  // poly exp on FMA pipe
            s += ex[r][q];
        }
        // reduce over j4 quad (lane bits 0,1)
        s += __shfl_xor_sync(0xffffffffu, s, 1);
        s += __shfl_xor_sync(0xffffffffu, s, 2);
        if (j4 == 0) pd[(i8 + 8 * r) * 8 + w] = s;
    }
    __syncthreads();

    // ---- total over 8 warps, normalize, write ----
    float* outbase = out + ((size_t)n * R_DIM + i0) * R_DIM + 16 * w + j4;
    #pragma unroll
    for (int r = 0; r < 4; ++r) {
        const int i = i8 + 8 * r;
        float4 p0 = *(const float4*)&pd[i * 8];
        float4 p1 = *(const float4*)&pd[i * 8 + 4];
        float tot = ((p0.x + p0.y) + (p0.z + p0.w)) + ((p1.x + p1.y) + (p1.z + p1.w));
        float inv = __fdividef(1.0f, tot);
        float* op = outbase + (size_t)i * R_DIM;
        #pragma unroll
        for (int q = 0; q < 4; ++q)
            op[4 * q] = ex[r][q] * inv;
    }
}

extern "C" void kernel_launch(void* const* d_in, const int* in_sizes, int n_in,
                              void* d_out, int out_size) {
    const float4* x1    = (const float4*)d_in[0];
    const float4* x2    = (const float4*)d_in[1];
    const float*  sigma = (const float*)d_in[2];
    const float*  mean  = (const float*)d_in[3];
    float* out = (float*)d_out;

    const int smem_bytes = (R_DIM * SSTR + TIB * SSTR + TIB + R_DIM + TIB * 8) * (int)sizeof(float);
    cudaFuncSetAttribute(gaussian_gram_v11,
                         cudaFuncAttributeMaxDynamicSharedMemorySize, smem_bytes);

    dim3 grid(R_DIM / TIB, N_B);   // (4, 32) = 128 blocks -> 1 per SM
    dim3 block(256);
    gaussian_gram_v11<<<grid, block, smem_bytes>>>(x1, x2, sigma, mean, out);
}